// round 3
// baseline (speedup 1.0000x reference)
#include <cuda_runtime.h>
#include <cuda_bf16.h>

// Problem constants
#define NB   2
#define NS   2048
#define NE   2048
#define NH   16
#define ND   128
#define N3E  6144

// Scratch (allocation-free rule: __device__ globals)
__device__ float g_q[(size_t)NB * NH * NS * ND];     // [B,H,S,D]
__device__ float g_k[(size_t)NB * NH * NS * ND];
__device__ float g_v[(size_t)NB * NH * NS * ND];
__device__ float g_attn[(size_t)NB * NS * NE];       // [B,S,E] attention output

// ---------------------------------------------------------------------------
// GEMM 1: qkv = x @ w_qkv^T + b_qkv, scattered into Q/K/V [B,H,S,D]
// A = x [4096, 2048] row-major, W = w_qkv [6144, 2048] row-major (both K-major)
// 128x128 tile, BK=16, 256 threads, 8x8 per thread.
// Each 128-wide n tile maps to exactly one (which, head): contiguous scatter.
// ---------------------------------------------------------------------------
__global__ __launch_bounds__(256) void gemm_qkv_kernel(
    const float* __restrict__ A, const float* __restrict__ W,
    const float* __restrict__ bias)
{
    __shared__ float As[16][132];
    __shared__ float Bs[16][132];

    const int K  = NE;
    const int m0 = blockIdx.y * 128;
    const int n0 = blockIdx.x * 128;
    const int tid = threadIdx.x;
    const int tr = tid >> 4, tc = tid & 15;
    const int lr = tid >> 2, lc = (tid & 3) << 2;

    float acc[8][8];
    #pragma unroll
    for (int i = 0; i < 8; i++)
        #pragma unroll
        for (int j = 0; j < 8; j++) acc[i][j] = 0.f;

    for (int k0 = 0; k0 < K; k0 += 16) {
        #pragma unroll
        for (int r = 0; r < 128; r += 64) {
            float4 va = *(const float4*)(A + (size_t)(m0 + lr + r) * K + k0 + lc);
            As[lc + 0][lr + r] = va.x; As[lc + 1][lr + r] = va.y;
            As[lc + 2][lr + r] = va.z; As[lc + 3][lr + r] = va.w;
            float4 vb = *(const float4*)(W + (size_t)(n0 + lr + r) * K + k0 + lc);
            Bs[lc + 0][lr + r] = vb.x; Bs[lc + 1][lr + r] = vb.y;
            Bs[lc + 2][lr + r] = vb.z; Bs[lc + 3][lr + r] = vb.w;
        }
        __syncthreads();
        #pragma unroll
        for (int kk = 0; kk < 16; kk++) {
            float a[8], b[8];
            *(float4*)&a[0] = *(const float4*)&As[kk][tr * 8];
            *(float4*)&a[4] = *(const float4*)&As[kk][tr * 8 + 4];
            *(float4*)&b[0] = *(const float4*)&Bs[kk][tc * 8];
            *(float4*)&b[4] = *(const float4*)&Bs[kk][tc * 8 + 4];
            #pragma unroll
            for (int i = 0; i < 8; i++)
                #pragma unroll
                for (int j = 0; j < 8; j++) acc[i][j] += a[i] * b[j];
        }
        __syncthreads();
    }

    // Scatter: n0 is a multiple of 128 -> whole tile belongs to one (which, h)
    const int which = n0 >> 11;            // 0=Q, 1=K, 2=V
    const int h     = (n0 & 2047) >> 7;    // head
    const int bb    = m0 >> 11;            // batch
    const int s0    = m0 & 2047;           // sequence base
    float* dst = (which == 0 ? g_q : (which == 1 ? g_k : g_v))
               + (((size_t)(bb * NH + h)) * NS + s0) * ND;
    #pragma unroll
    for (int i = 0; i < 8; i++) {
        #pragma unroll
        for (int j = 0; j < 8; j++) {
            const int col = tc * 8 + j;
            dst[(size_t)(tr * 8 + i) * ND + col] = acc[i][j] + bias[n0 + col];
        }
    }
}

// ---------------------------------------------------------------------------
// GEMM 2: out = attn @ w_out^T + b_out  (plain [4096,2048] output)
// ---------------------------------------------------------------------------
__global__ __launch_bounds__(256) void gemm_out_kernel(
    const float* __restrict__ W, const float* __restrict__ bias,
    float* __restrict__ C)
{
    __shared__ float As[16][132];
    __shared__ float Bs[16][132];

    const float* A = g_attn;
    const int K  = NE;
    const int m0 = blockIdx.y * 128;
    const int n0 = blockIdx.x * 128;
    const int tid = threadIdx.x;
    const int tr = tid >> 4, tc = tid & 15;
    const int lr = tid >> 2, lc = (tid & 3) << 2;

    float acc[8][8];
    #pragma unroll
    for (int i = 0; i < 8; i++)
        #pragma unroll
        for (int j = 0; j < 8; j++) acc[i][j] = 0.f;

    for (int k0 = 0; k0 < K; k0 += 16) {
        #pragma unroll
        for (int r = 0; r < 128; r += 64) {
            float4 va = *(const float4*)(A + (size_t)(m0 + lr + r) * K + k0 + lc);
            As[lc + 0][lr + r] = va.x; As[lc + 1][lr + r] = va.y;
            As[lc + 2][lr + r] = va.z; As[lc + 3][lr + r] = va.w;
            float4 vb = *(const float4*)(W + (size_t)(n0 + lr + r) * K + k0 + lc);
            Bs[lc + 0][lr + r] = vb.x; Bs[lc + 1][lr + r] = vb.y;
            Bs[lc + 2][lr + r] = vb.z; Bs[lc + 3][lr + r] = vb.w;
        }
        __syncthreads();
        #pragma unroll
        for (int kk = 0; kk < 16; kk++) {
            float a[8], b[8];
            *(float4*)&a[0] = *(const float4*)&As[kk][tr * 8];
            *(float4*)&a[4] = *(const float4*)&As[kk][tr * 8 + 4];
            *(float4*)&b[0] = *(const float4*)&Bs[kk][tc * 8];
            *(float4*)&b[4] = *(const float4*)&Bs[kk][tc * 8 + 4];
            #pragma unroll
            for (int i = 0; i < 8; i++)
                #pragma unroll
                for (int j = 0; j < 8; j++) acc[i][j] += a[i] * b[j];
        }
        __syncthreads();
    }

    #pragma unroll
    for (int i = 0; i < 8; i++) {
        #pragma unroll
        for (int j = 0; j < 8; j++) {
            const int col = n0 + tc * 8 + j;
            C[(size_t)(m0 + tr * 8 + i) * NE + col] = acc[i][j] + bias[col];
        }
    }
}

// ---------------------------------------------------------------------------
// Flash attention, causal. One CTA per (b*h, q-tile of 128). 256 threads.
// BKV = 64. Online softmax. Dynamic smem partitions:
//   As  [16][132]  transposed Q d-chunk
//   Bs  [16][68]   transposed K d-chunk
//   Pts [64][132]  P transposed (kv-major) for the PV micro-GEMM
//   Vs  [64][132]  V tile
// ---------------------------------------------------------------------------
#define ATT_SMEM_FLOATS (16*132 + 16*68 + 64*132 + 64*132)
#define ATT_SMEM_BYTES  (ATT_SMEM_FLOATS * 4)

__global__ __launch_bounds__(256) void attn_kernel()
{
    extern __shared__ float sm[];
    float* As  = sm;                       // 2112 floats
    float* Bs  = As + 16 * 132;            // 1088 floats
    float* Pts = Bs + 16 * 68;             // 8448 floats
    float* Vs  = Pts + 64 * 132;           // 8448 floats

    const int qt = blockIdx.x;             // 0..15
    const int bh = blockIdx.y;             // 0..31
    const int q0 = qt * 128;
    const float* Qg = g_q + (size_t)bh * NS * ND;
    const float* Kg = g_k + (size_t)bh * NS * ND;
    const float* Vg = g_v + (size_t)bh * NS * ND;

    const int tid = threadIdx.x;
    const int tr = tid >> 4;               // q rows tr*8..+7
    const int tc = tid & 15;               // score: k cols tc*4..+3 ; PV: d cols tc*8..+7
    const int lr = tid >> 2, lc = (tid & 3) << 2;

    const float scale = 0.08838834764831845f;   // 1/sqrt(128)

    float m_i[8], l_i[8], o[8][8];
    #pragma unroll
    for (int i = 0; i < 8; i++) {
        m_i[i] = -1e30f; l_i[i] = 0.f;
        #pragma unroll
        for (int j = 0; j < 8; j++) o[i][j] = 0.f;
    }

    const int nkv = 2 * qt + 2;            // causal: only tiles with kv <= q max

    for (int kt = 0; kt < nkv; kt++) {
        const int kv0 = kt * 64;

        // ---- V tile load (coalesced; row pad 132 keeps float4 alignment) ----
        #pragma unroll
        for (int u = 0; u < 8; u++) {
            const int idx = tid + 256 * u;           // 0..2047 float4s
            const int r = idx >> 5, c = (idx & 31) << 2;
            *(float4*)(Vs + r * 132 + c) =
                *(const float4*)(Vg + (size_t)(kv0 + r) * ND + c);
        }

        // ---- score phase: S = Q(128xD) @ K^T, d streamed in 16-chunks ----
        float sacc[8][4];
        #pragma unroll
        for (int i = 0; i < 8; i++)
            #pragma unroll
            for (int j = 0; j < 4; j++) sacc[i][j] = 0.f;

        for (int d0 = 0; d0 < ND; d0 += 16) {
            __syncthreads();   // As/Bs reuse between chunks
            #pragma unroll
            for (int r = 0; r < 128; r += 64) {
                float4 t = *(const float4*)(Qg + (size_t)(q0 + lr + r) * ND + d0 + lc);
                As[(lc + 0) * 132 + lr + r] = t.x;
                As[(lc + 1) * 132 + lr + r] = t.y;
                As[(lc + 2) * 132 + lr + r] = t.z;
                As[(lc + 3) * 132 + lr + r] = t.w;
            }
            {
                float4 t = *(const float4*)(Kg + (size_t)(kv0 + lr) * ND + d0 + lc);
                Bs[(lc + 0) * 68 + lr] = t.x;
                Bs[(lc + 1) * 68 + lr] = t.y;
                Bs[(lc + 2) * 68 + lr] = t.z;
                Bs[(lc + 3) * 68 + lr] = t.w;
            }
            __syncthreads();
            #pragma unroll
            for (int dk = 0; dk < 16; dk++) {
                float a[8], b[4];
                *(float4*)&a[0] = *(const float4*)&As[dk * 132 + tr * 8];
                *(float4*)&a[4] = *(const float4*)&As[dk * 132 + tr * 8 + 4];
                *(float4*)&b[0] = *(const float4*)&Bs[dk * 68 + tc * 4];
                #pragma unroll
                for (int i = 0; i < 8; i++)
                    #pragma unroll
                    for (int j = 0; j < 4; j++) sacc[i][j] += a[i] * b[j];
            }
        }

        // ---- scale + causal mask + online softmax update (16-lane groups) ----
        #pragma unroll
        for (int i = 0; i < 8; i++) {
            const int qg = q0 + tr * 8 + i;
            #pragma unroll
            for (int j = 0; j < 4; j++) {
                const int kg = kv0 + tc * 4 + j;
                const float sv = sacc[i][j] * scale;
                sacc[i][j] = (kg > qg) ? -1e30f : sv;
            }
            float mx = fmaxf(fmaxf(sacc[i][0], sacc[i][1]),
                             fmaxf(sacc[i][2], sacc[i][3]));
            #pragma unroll
            for (int off = 8; off > 0; off >>= 1)
                mx = fmaxf(mx, __shfl_xor_sync(0xffffffffu, mx, off));
            const float mnew = fmaxf(m_i[i], mx);
            float rs = 0.f;
            #pragma unroll
            for (int j = 0; j < 4; j++) {
                const float p = __expf(sacc[i][j] - mnew);
                sacc[i][j] = p;
                rs += p;
            }
            #pragma unroll
            for (int off = 8; off > 0; off >>= 1)
                rs += __shfl_xor_sync(0xffffffffu, rs, off);
            const float fac = __expf(m_i[i] - mnew);
            l_i[i] = l_i[i] * fac + rs;
            m_i[i] = mnew;
            #pragma unroll
            for (int j = 0; j < 8; j++) o[i][j] *= fac;
        }

        // ---- P -> shared (transposed, kv-major) ----
        #pragma unroll
        for (int i = 0; i < 8; i++)
            #pragma unroll
            for (int j = 0; j < 4; j++)
                Pts[(tc * 4 + j) * 132 + tr * 8 + i] = sacc[i][j];
        __syncthreads();

        // ---- PV: O += P(128x64) @ V(64x128) ----
        #pragma unroll 4
        for (int kk = 0; kk < 64; kk++) {
            float a[8], b[8];
            *(float4*)&a[0] = *(const float4*)&Pts[kk * 132 + tr * 8];
            *(float4*)&a[4] = *(const float4*)&Pts[kk * 132 + tr * 8 + 4];
            *(float4*)&b[0] = *(const float4*)&Vs[kk * 132 + tc * 8];
            *(float4*)&b[4] = *(const float4*)&Vs[kk * 132 + tc * 8 + 4];
            #pragma unroll
            for (int i = 0; i < 8; i++)
                #pragma unroll
                for (int j = 0; j < 8; j++) o[i][j] += a[i] * b[j];
        }
        __syncthreads();   // protects Vs/Pts overwrite next tile
    }

    // ---- epilogue: normalize and write [B,S,E] with head offset ----
    const int bb = bh / NH, h = bh % NH;
    #pragma unroll
    for (int i = 0; i < 8; i++) {
        const float inv = 1.0f / l_i[i];
        const int s = q0 + tr * 8 + i;
        float* dp = g_attn + ((size_t)bb * NS + s) * NE + h * ND + tc * 8;
        #pragma unroll
        for (int j = 0; j < 8; j++) dp[j] = o[i][j] * inv;
    }
}

// ---------------------------------------------------------------------------
// Launch. Inputs (metadata order): x, attn_mask(unused; causal is static),
// w_qkv, b_qkv, w_out, b_out. Output: [B,S,E] fp32.
// ---------------------------------------------------------------------------
extern "C" void kernel_launch(void* const* d_in, const int* in_sizes, int n_in,
                              void* d_out, int out_size)
{
    (void)in_sizes; (void)n_in; (void)out_size;
    const float* x     = (const float*)d_in[0];
    const float* w_qkv = (const float*)d_in[2];
    const float* b_qkv = (const float*)d_in[3];
    const float* w_out = (const float*)d_in[4];
    const float* b_out = (const float*)d_in[5];
    float* out = (float*)d_out;

    // Idempotent; legal during graph capture (non-stream API, and the
    // pre-capture correctness call already applied it).
    cudaFuncSetAttribute(attn_kernel,
                         cudaFuncAttributeMaxDynamicSharedMemorySize,
                         ATT_SMEM_BYTES);

    dim3 g1(N3E / 128, (NB * NS) / 128);   // (48, 32)
    gemm_qkv_kernel<<<g1, 256>>>(x, w_qkv, b_qkv);

    dim3 g2(NS / 128, NB * NH);            // (16, 32)
    attn_kernel<<<g2, 256, ATT_SMEM_BYTES>>>();

    dim3 g3(NE / 128, (NB * NS) / 128);    // (16, 32)
    gemm_out_kernel<<<g3, 256>>>(w_out, b_out, out);
}

// round 4
// speedup vs baseline: 1.0001x; 1.0001x over previous
#include <cuda_runtime.h>
#include <cuda_bf16.h>

// Problem constants
#define NB   2
#define NS   2048
#define NE   2048
#define NH   16
#define ND   128
#define N3E  6144

// Scratch (allocation-free rule: __device__ globals)
__device__ float g_q[(size_t)NB * NH * NS * ND];     // [B,H,S,D]
__device__ float g_k[(size_t)NB * NH * NS * ND];
__device__ float g_v[(size_t)NB * NH * NS * ND];
__device__ float g_attn[(size_t)NB * NS * NE];       // [B,S,E] attention output

// ---------------------------------------------------------------------------
// GEMM 1: qkv = x @ w_qkv^T + b_qkv, scattered into Q/K/V [B,H,S,D]
// A = x [4096, 2048] row-major, W = w_qkv [6144, 2048] row-major (both K-major)
// 128x128 tile, BK=16, 256 threads, 8x8 per thread.
// Each 128-wide n tile maps to exactly one (which, head): contiguous scatter.
// ---------------------------------------------------------------------------
__global__ __launch_bounds__(256) void gemm_qkv_kernel(
    const float* __restrict__ A, const float* __restrict__ W,
    const float* __restrict__ bias)
{
    __shared__ float As[16][132];
    __shared__ float Bs[16][132];

    const int K  = NE;
    const int m0 = blockIdx.y * 128;
    const int n0 = blockIdx.x * 128;
    const int tid = threadIdx.x;
    const int tr = tid >> 4, tc = tid & 15;
    const int lr = tid >> 2, lc = (tid & 3) << 2;

    float acc[8][8];
    #pragma unroll
    for (int i = 0; i < 8; i++)
        #pragma unroll
        for (int j = 0; j < 8; j++) acc[i][j] = 0.f;

    for (int k0 = 0; k0 < K; k0 += 16) {
        #pragma unroll
        for (int r = 0; r < 128; r += 64) {
            float4 va = *(const float4*)(A + (size_t)(m0 + lr + r) * K + k0 + lc);
            As[lc + 0][lr + r] = va.x; As[lc + 1][lr + r] = va.y;
            As[lc + 2][lr + r] = va.z; As[lc + 3][lr + r] = va.w;
            float4 vb = *(const float4*)(W + (size_t)(n0 + lr + r) * K + k0 + lc);
            Bs[lc + 0][lr + r] = vb.x; Bs[lc + 1][lr + r] = vb.y;
            Bs[lc + 2][lr + r] = vb.z; Bs[lc + 3][lr + r] = vb.w;
        }
        __syncthreads();
        #pragma unroll
        for (int kk = 0; kk < 16; kk++) {
            float a[8], b[8];
            *(float4*)&a[0] = *(const float4*)&As[kk][tr * 8];
            *(float4*)&a[4] = *(const float4*)&As[kk][tr * 8 + 4];
            *(float4*)&b[0] = *(const float4*)&Bs[kk][tc * 8];
            *(float4*)&b[4] = *(const float4*)&Bs[kk][tc * 8 + 4];
            #pragma unroll
            for (int i = 0; i < 8; i++)
                #pragma unroll
                for (int j = 0; j < 8; j++) acc[i][j] += a[i] * b[j];
        }
        __syncthreads();
    }

    // Scatter: n0 is a multiple of 128 -> whole tile belongs to one (which, h)
    const int which = n0 >> 11;            // 0=Q, 1=K, 2=V
    const int h     = (n0 & 2047) >> 7;    // head
    const int bb    = m0 >> 11;            // batch
    const int s0    = m0 & 2047;           // sequence base
    float* dst = (which == 0 ? g_q : (which == 1 ? g_k : g_v))
               + (((size_t)(bb * NH + h)) * NS + s0) * ND;
    #pragma unroll
    for (int i = 0; i < 8; i++) {
        #pragma unroll
        for (int j = 0; j < 8; j++) {
            const int col = tc * 8 + j;
            dst[(size_t)(tr * 8 + i) * ND + col] = acc[i][j] + bias[n0 + col];
        }
    }
}

// ---------------------------------------------------------------------------
// GEMM 2: out = attn @ w_out^T + b_out  (plain [4096,2048] output)
// ---------------------------------------------------------------------------
__global__ __launch_bounds__(256) void gemm_out_kernel(
    const float* __restrict__ W, const float* __restrict__ bias,
    float* __restrict__ C)
{
    __shared__ float As[16][132];
    __shared__ float Bs[16][132];

    const float* A = g_attn;
    const int K  = NE;
    const int m0 = blockIdx.y * 128;
    const int n0 = blockIdx.x * 128;
    const int tid = threadIdx.x;
    const int tr = tid >> 4, tc = tid & 15;
    const int lr = tid >> 2, lc = (tid & 3) << 2;

    float acc[8][8];
    #pragma unroll
    for (int i = 0; i < 8; i++)
        #pragma unroll
        for (int j = 0; j < 8; j++) acc[i][j] = 0.f;

    for (int k0 = 0; k0 < K; k0 += 16) {
        #pragma unroll
        for (int r = 0; r < 128; r += 64) {
            float4 va = *(const float4*)(A + (size_t)(m0 + lr + r) * K + k0 + lc);
            As[lc + 0][lr + r] = va.x; As[lc + 1][lr + r] = va.y;
            As[lc + 2][lr + r] = va.z; As[lc + 3][lr + r] = va.w;
            float4 vb = *(const float4*)(W + (size_t)(n0 + lr + r) * K + k0 + lc);
            Bs[lc + 0][lr + r] = vb.x; Bs[lc + 1][lr + r] = vb.y;
            Bs[lc + 2][lr + r] = vb.z; Bs[lc + 3][lr + r] = vb.w;
        }
        __syncthreads();
        #pragma unroll
        for (int kk = 0; kk < 16; kk++) {
            float a[8], b[8];
            *(float4*)&a[0] = *(const float4*)&As[kk][tr * 8];
            *(float4*)&a[4] = *(const float4*)&As[kk][tr * 8 + 4];
            *(float4*)&b[0] = *(const float4*)&Bs[kk][tc * 8];
            *(float4*)&b[4] = *(const float4*)&Bs[kk][tc * 8 + 4];
            #pragma unroll
            for (int i = 0; i < 8; i++)
                #pragma unroll
                for (int j = 0; j < 8; j++) acc[i][j] += a[i] * b[j];
        }
        __syncthreads();
    }

    #pragma unroll
    for (int i = 0; i < 8; i++) {
        #pragma unroll
        for (int j = 0; j < 8; j++) {
            const int col = n0 + tc * 8 + j;
            C[(size_t)(m0 + tr * 8 + i) * NE + col] = acc[i][j] + bias[col];
        }
    }
}

// ---------------------------------------------------------------------------
// Flash attention, causal. One CTA per (b*h, q-tile of 128). 256 threads.
// BKV = 64. Online softmax. Dynamic smem partitions:
//   As  [16][132]  transposed Q d-chunk
//   Bs  [16][68]   transposed K d-chunk
//   Pts [64][132]  P transposed (kv-major) for the PV micro-GEMM
//   Vs  [64][132]  V tile
// ---------------------------------------------------------------------------
#define ATT_SMEM_FLOATS (16*132 + 16*68 + 64*132 + 64*132)
#define ATT_SMEM_BYTES  (ATT_SMEM_FLOATS * 4)

__global__ __launch_bounds__(256) void attn_kernel()
{
    extern __shared__ float sm[];
    float* As  = sm;                       // 2112 floats
    float* Bs  = As + 16 * 132;            // 1088 floats
    float* Pts = Bs + 16 * 68;             // 8448 floats
    float* Vs  = Pts + 64 * 132;           // 8448 floats

    const int qt = blockIdx.x;             // 0..15
    const int bh = blockIdx.y;             // 0..31
    const int q0 = qt * 128;
    const float* Qg = g_q + (size_t)bh * NS * ND;
    const float* Kg = g_k + (size_t)bh * NS * ND;
    const float* Vg = g_v + (size_t)bh * NS * ND;

    const int tid = threadIdx.x;
    const int tr = tid >> 4;               // q rows tr*8..+7
    const int tc = tid & 15;               // score: k cols tc*4..+3 ; PV: d cols tc*8..+7
    const int lr = tid >> 2, lc = (tid & 3) << 2;

    const float scale = 0.08838834764831845f;   // 1/sqrt(128)

    float m_i[8], l_i[8], o[8][8];
    #pragma unroll
    for (int i = 0; i < 8; i++) {
        m_i[i] = -1e30f; l_i[i] = 0.f;
        #pragma unroll
        for (int j = 0; j < 8; j++) o[i][j] = 0.f;
    }

    const int nkv = 2 * qt + 2;            // causal: only tiles with kv <= q max

    for (int kt = 0; kt < nkv; kt++) {
        const int kv0 = kt * 64;

        // ---- V tile load (coalesced; row pad 132 keeps float4 alignment) ----
        #pragma unroll
        for (int u = 0; u < 8; u++) {
            const int idx = tid + 256 * u;           // 0..2047 float4s
            const int r = idx >> 5, c = (idx & 31) << 2;
            *(float4*)(Vs + r * 132 + c) =
                *(const float4*)(Vg + (size_t)(kv0 + r) * ND + c);
        }

        // ---- score phase: S = Q(128xD) @ K^T, d streamed in 16-chunks ----
        float sacc[8][4];
        #pragma unroll
        for (int i = 0; i < 8; i++)
            #pragma unroll
            for (int j = 0; j < 4; j++) sacc[i][j] = 0.f;

        for (int d0 = 0; d0 < ND; d0 += 16) {
            __syncthreads();   // As/Bs reuse between chunks
            #pragma unroll
            for (int r = 0; r < 128; r += 64) {
                float4 t = *(const float4*)(Qg + (size_t)(q0 + lr + r) * ND + d0 + lc);
                As[(lc + 0) * 132 + lr + r] = t.x;
                As[(lc + 1) * 132 + lr + r] = t.y;
                As[(lc + 2) * 132 + lr + r] = t.z;
                As[(lc + 3) * 132 + lr + r] = t.w;
            }
            {
                float4 t = *(const float4*)(Kg + (size_t)(kv0 + lr) * ND + d0 + lc);
                Bs[(lc + 0) * 68 + lr] = t.x;
                Bs[(lc + 1) * 68 + lr] = t.y;
                Bs[(lc + 2) * 68 + lr] = t.z;
                Bs[(lc + 3) * 68 + lr] = t.w;
            }
            __syncthreads();
            #pragma unroll
            for (int dk = 0; dk < 16; dk++) {
                float a[8], b[4];
                *(float4*)&a[0] = *(const float4*)&As[dk * 132 + tr * 8];
                *(float4*)&a[4] = *(const float4*)&As[dk * 132 + tr * 8 + 4];
                *(float4*)&b[0] = *(const float4*)&Bs[dk * 68 + tc * 4];
                #pragma unroll
                for (int i = 0; i < 8; i++)
                    #pragma unroll
                    for (int j = 0; j < 4; j++) sacc[i][j] += a[i] * b[j];
            }
        }

        // ---- scale + causal mask + online softmax update (16-lane groups) ----
        #pragma unroll
        for (int i = 0; i < 8; i++) {
            const int qg = q0 + tr * 8 + i;
            #pragma unroll
            for (int j = 0; j < 4; j++) {
                const int kg = kv0 + tc * 4 + j;
                const float sv = sacc[i][j] * scale;
                sacc[i][j] = (kg > qg) ? -1e30f : sv;
            }
            float mx = fmaxf(fmaxf(sacc[i][0], sacc[i][1]),
                             fmaxf(sacc[i][2], sacc[i][3]));
            #pragma unroll
            for (int off = 8; off > 0; off >>= 1)
                mx = fmaxf(mx, __shfl_xor_sync(0xffffffffu, mx, off));
            const float mnew = fmaxf(m_i[i], mx);
            float rs = 0.f;
            #pragma unroll
            for (int j = 0; j < 4; j++) {
                const float p = __expf(sacc[i][j] - mnew);
                sacc[i][j] = p;
                rs += p;
            }
            #pragma unroll
            for (int off = 8; off > 0; off >>= 1)
                rs += __shfl_xor_sync(0xffffffffu, rs, off);
            const float fac = __expf(m_i[i] - mnew);
            l_i[i] = l_i[i] * fac + rs;
            m_i[i] = mnew;
            #pragma unroll
            for (int j = 0; j < 8; j++) o[i][j] *= fac;
        }

        // ---- P -> shared (transposed, kv-major) ----
        #pragma unroll
        for (int i = 0; i < 8; i++)
            #pragma unroll
            for (int j = 0; j < 4; j++)
                Pts[(tc * 4 + j) * 132 + tr * 8 + i] = sacc[i][j];
        __syncthreads();

        // ---- PV: O += P(128x64) @ V(64x128) ----
        #pragma unroll 4
        for (int kk = 0; kk < 64; kk++) {
            float a[8], b[8];
            *(float4*)&a[0] = *(const float4*)&Pts[kk * 132 + tr * 8];
            *(float4*)&a[4] = *(const float4*)&Pts[kk * 132 + tr * 8 + 4];
            *(float4*)&b[0] = *(const float4*)&Vs[kk * 132 + tc * 8];
            *(float4*)&b[4] = *(const float4*)&Vs[kk * 132 + tc * 8 + 4];
            #pragma unroll
            for (int i = 0; i < 8; i++)
                #pragma unroll
                for (int j = 0; j < 8; j++) o[i][j] += a[i] * b[j];
        }
        __syncthreads();   // protects Vs/Pts overwrite next tile
    }

    // ---- epilogue: normalize and write [B,S,E] with head offset ----
    const int bb = bh / NH, h = bh % NH;
    #pragma unroll
    for (int i = 0; i < 8; i++) {
        const float inv = 1.0f / l_i[i];
        const int s = q0 + tr * 8 + i;
        float* dp = g_attn + ((size_t)bb * NS + s) * NE + h * ND + tc * 8;
        #pragma unroll
        for (int j = 0; j < 8; j++) dp[j] = o[i][j] * inv;
    }
}

// ---------------------------------------------------------------------------
// Launch. Inputs (metadata order): x, attn_mask(unused; causal is static),
// w_qkv, b_qkv, w_out, b_out. Output: [B,S,E] fp32.
// ---------------------------------------------------------------------------
extern "C" void kernel_launch(void* const* d_in, const int* in_sizes, int n_in,
                              void* d_out, int out_size)
{
    (void)in_sizes; (void)n_in; (void)out_size;
    const float* x     = (const float*)d_in[0];
    const float* w_qkv = (const float*)d_in[2];
    const float* b_qkv = (const float*)d_in[3];
    const float* w_out = (const float*)d_in[4];
    const float* b_out = (const float*)d_in[5];
    float* out = (float*)d_out;

    // Idempotent; legal during graph capture (non-stream API, and the
    // pre-capture correctness call already applied it).
    cudaFuncSetAttribute(attn_kernel,
                         cudaFuncAttributeMaxDynamicSharedMemorySize,
                         ATT_SMEM_BYTES);

    dim3 g1(N3E / 128, (NB * NS) / 128);   // (48, 32)
    gemm_qkv_kernel<<<g1, 256>>>(x, w_qkv, b_qkv);

    dim3 g2(NS / 128, NB * NH);            // (16, 32)
    attn_kernel<<<g2, 256, ATT_SMEM_BYTES>>>();

    dim3 g3(NE / 128, (NB * NS) / 128);    // (16, 32)
    gemm_out_kernel<<<g3, 256>>>(w_out, b_out, out);
}